// round 10
// baseline (speedup 1.0000x reference)
#include <cuda_runtime.h>
#include <cstdint>
#include <cstddef>

#define S_   250
#define N_   200
#define MAXC 16
#define H_   64
#define HID_ 512
#define BN_  32
#define NPED (S_*N_)

// ---- scratch (static __device__ arrays: allocation-free) ----
__device__ __align__(16) static float g_Y[(size_t)NPED * HID_];   // h @ W1[:64] + b1p
__device__               static int   g_sel[NPED * MAXC];         // ranks
__device__ __align__(16) static float g_wpe[2 * HID_];            // W_pos @ W1[64:]
__device__ __align__(16) static float g_b1p[HID_];                // b1 + b_pos @ W1[64:]

// ---- packed f32x2 helpers ----
#define FMA2(d, a, b) asm("fma.rn.f32x2 %0, %1, %2, %0;" : "+l"(d) : "l"(a), "l"(b))
#define PACK_DUP(d, x) asm("mov.b64 %0, {%1, %1};" : "=l"(d) : "f"(x))
#define UNPK(lo, hi, v) asm("mov.b64 {%0, %1}, %2;" : "=f"(lo), "=f"(hi) : "l"(v))

__global__ void prep_kernel(const float* __restrict__ W_pos, const float* __restrict__ b_pos,
                            const float* __restrict__ W1,    const float* __restrict__ b1) {
    int t = threadIdx.x; // 512 threads
    float s0 = 0.f, s1 = 0.f, sb = 0.f;
    for (int e = 0; e < 64; ++e) {
        float w = W1[(size_t)(64 + e) * HID_ + t];
        s0 += W_pos[e] * w;
        s1 += W_pos[64 + e] * w;
        sb += b_pos[e] * w;
    }
    g_wpe[t] = s0;
    g_wpe[HID_ + t] = s1;
    g_b1p[t] = b1[t] + sb;
}

__device__ __forceinline__ float distf(const float* px, const float* py,
                                       int j, float xi, float yi) {
    float dx = px[j] - xi;
    float dy = py[j] - yi;
    return __fsqrt_rn(__fadd_rn(__fmul_rn(dx, dx), __fmul_rn(dy, dy)));
}

__global__ void rank_kernel(const float* __restrict__ lp) {
    int s = blockIdx.y;
    __shared__ float px[N_], py[N_];
    int tid = threadIdx.x;
    for (int j = tid; j < N_; j += 256) {
        px[j] = lp[(size_t)(s * N_ + j) * 2];
        py[j] = lp[(size_t)(s * N_ + j) * 2 + 1];
    }
    __syncthreads();
    int w = tid >> 5, lane = tid & 31;
    int i = blockIdx.x * 8 + w;
    float xi = px[i], yi = py[i];

    float dl = distf(px, py, lane, xi, yi);
    float dm[MAXC];
#pragma unroll
    for (int m = 0; m < MAXC; ++m) dm[m] = __shfl_sync(0xffffffffu, dl, m);

    int cnt[MAXC];
#pragma unroll
    for (int m = 0; m < MAXC; ++m) cnt[m] = 0;
    for (int j = lane; j < N_; j += 32) {
        float d = distf(px, py, j, xi, yi);
#pragma unroll
        for (int m = 0; m < MAXC; ++m)
            cnt[m] += (int)((d < dm[m]) || (d == dm[m] && j < m));
    }
    int myr = 0;
#pragma unroll
    for (int m = 0; m < MAXC; ++m) {
        int tot = __reduce_add_sync(0xffffffffu, cnt[m]);
        if (lane == m) myr = tot;
    }
    if (lane < MAXC) g_sel[(s * N_ + i) * MAXC + lane] = myr;
}

__global__ void y_kernel(const float* __restrict__ h, const float* __restrict__ W1) {
    __shared__ __align__(16) float Ash[64 * 65];
    __shared__ __align__(16) float Bsh[64 * 64];
    int tid = threadIdx.x;
    int row0 = blockIdx.x * 64;
    int c0   = blockIdx.y * 64;
#pragma unroll
    for (int q = 0; q < 4; ++q) {
        int idx4 = tid + 256 * q;
        int row = idx4 >> 4, k4 = (idx4 & 15) << 2;
        float4 v = make_float4(0.f, 0.f, 0.f, 0.f);
        if (row0 + row < NPED) v = *(const float4*)&h[(size_t)(row0 + row) * H_ + k4];
        Ash[row * 65 + k4 + 0] = v.x; Ash[row * 65 + k4 + 1] = v.y;
        Ash[row * 65 + k4 + 2] = v.z; Ash[row * 65 + k4 + 3] = v.w;
    }
#pragma unroll
    for (int q = 0; q < 4; ++q) {
        int idx4 = tid + 256 * q;
        int k = idx4 >> 4, c4 = (idx4 & 15) << 2;
        *(float4*)&Bsh[k * 64 + c4] = *(const float4*)&W1[(size_t)k * HID_ + c0 + c4];
    }
    __syncthreads();
    int rg = tid >> 4, cg = tid & 15;
    float acc[4][4] = {};
#pragma unroll 16
    for (int k = 0; k < 64; ++k) {
        float a[4];
#pragma unroll
        for (int r = 0; r < 4; ++r) a[r] = Ash[(rg * 4 + r) * 65 + k];
        float4 b = *(const float4*)&Bsh[k * 64 + cg * 4];
#pragma unroll
        for (int r = 0; r < 4; ++r) {
            acc[r][0] += a[r] * b.x; acc[r][1] += a[r] * b.y;
            acc[r][2] += a[r] * b.z; acc[r][3] += a[r] * b.w;
        }
    }
    float4 bb = *(const float4*)&g_b1p[c0 + cg * 4];
#pragma unroll
    for (int r = 0; r < 4; ++r) {
        int row = row0 + rg * 4 + r;
        if (row < NPED)
            *(float4*)&g_Y[(size_t)row * HID_ + c0 + cg * 4] =
                make_float4(acc[r][0] + bb.x, acc[r][1] + bb.y,
                            acc[r][2] + bb.z, acc[r][3] + bb.w);
    }
}

// =====================================================================
// fused: chunked pipeline; coalesced gather -> X1T smem -> f32x2 GEMM
// thread tile: 4 rows x 16 cols.  half = tid>>6 (warp-uniform -> W2
// broadcast); g = tid&63 owns rows {g, g+64, g+128, g+192} (conflict-free).
// =====================================================================
#define KC     32
#define X1TS   257
#define O_X1T  0
#define O_W2C  8704
#define O_WP0  9728
#define O_WP1  10240
#define O_PX   10752
#define O_PY   10952
#define O_FX   11152
#define O_FY   11408
#define O_YR   11664
#define O_B2   11920
#define O_BAT  11952
#define SM_FLOATS 11968

__global__ __launch_bounds__(128, 3) void fused_kernel(
    const float* __restrict__ lp, const float* __restrict__ W2g,
    const float* __restrict__ b2g, const float* __restrict__ Wag,
    const float* __restrict__ bag, float* __restrict__ out) {
    extern __shared__ __align__(16) float sm[];
    float* X1T  = sm + O_X1T;
    float* W2c  = sm + O_W2C;
    float* wp0s = sm + O_WP0;
    float* wp1s = sm + O_WP1;
    float* px   = sm + O_PX;
    float* py   = sm + O_PY;
    float* fxs  = sm + O_FX;
    float* fys  = sm + O_FY;
    int*   yr   = (int*)(sm + O_YR);
    float* b2s  = sm + O_B2;
    float* bats = sm + O_BAT;

    const int tid  = threadIdx.x;
    const int w    = tid >> 5, lane = tid & 31;
    const int s    = blockIdx.y;
    const int pg   = blockIdx.x;
    const int base = s * N_;

    for (int k = tid; k < HID_; k += 128) {
        wp0s[k] = g_wpe[k];
        wp1s[k] = g_wpe[HID_ + k];
    }
    for (int j = tid; j < N_; j += 128) {
        float2 p = *(const float2*)&lp[(size_t)(base + j) * 2];
        px[j] = p.x; py[j] = p.y;
    }
    if (tid < BN_)  b2s[tid]  = b2g[tid];
    if (tid < MAXC) bats[tid] = bag[tid];
    __syncthreads();

    for (int o = tid; o < 256; o += 128) {
        int ped = o >> 4, m = o & 15;
        int ig = min(pg * 16 + ped, N_ - 1);
        int rk = g_sel[(base + ig) * MAXC + m];
        yr[o]  = base + rk;
        fxs[o] = px[rk] - px[ig];
        fys[o] = py[rk] - py[ig];
    }
    __syncthreads();

    // ---- thread tile: rows {g,g+64,g+128,g+192} x cols [half*16, half*16+16)
    const int half = tid >> 6;
    const int g    = tid & 63;

    unsigned long long acc[4][8];
#pragma unroll
    for (int q = 0; q < 8; ++q) {
        unsigned long long b = *(const unsigned long long*)&b2s[half * 16 + 2 * q];
        acc[0][q] = b; acc[1][q] = b; acc[2][q] = b; acc[3][q] = b;
    }

    const int r_in = w * 64 + (lane >> 3);   // build-phase row base
    const int k4   = (lane & 7) << 2;        // build-phase k offset

    for (int c = 0; c < 16; ++c) {
        const int k0 = c * KC;
        // ---- build X1T chunk (coalesced gather) ----
        float4 wv0 = *(const float4*)&wp0s[k0 + k4];
        float4 wv1 = *(const float4*)&wp1s[k0 + k4];
#pragma unroll
        for (int rr = 0; rr < 16; ++rr) {
            int r = r_in + rr * 4;
            float4 y = *(const float4*)&g_Y[(size_t)yr[r] * HID_ + k0 + k4];
            float fx = fxs[r], fy = fys[r];
            X1T[(k4 + 0) * X1TS + r] = fmaxf(fmaf(fx, wv0.x, fmaf(fy, wv1.x, y.x)), 0.f);
            X1T[(k4 + 1) * X1TS + r] = fmaxf(fmaf(fx, wv0.y, fmaf(fy, wv1.y, y.y)), 0.f);
            X1T[(k4 + 2) * X1TS + r] = fmaxf(fmaf(fx, wv0.z, fmaf(fy, wv1.z, y.z)), 0.f);
            X1T[(k4 + 3) * X1TS + r] = fmaxf(fmaf(fx, wv0.w, fmaf(fy, wv1.w, y.w)), 0.f);
        }
        // ---- W2 chunk: 1024 floats, coalesced ----
        *(float4*)&W2c[tid * 4]         = *(const float4*)&W2g[(size_t)k0 * 32 + tid * 4];
        *(float4*)&W2c[(tid + 128) * 4] = *(const float4*)&W2g[(size_t)k0 * 32 + (tid + 128) * 4];
        __syncthreads();

        // ---- consume: 32 k-steps, 4 rows x 16 cols per thread ----
#pragma unroll 4
        for (int kk = 0; kk < KC; ++kk) {
            const float* xrow = &X1T[kk * X1TS];
            float x0 = xrow[g];
            float x1 = xrow[g + 64];
            float x2 = xrow[g + 128];
            float x3 = xrow[g + 192];
            unsigned long long a0, a1, a2, a3;
            PACK_DUP(a0, x0); PACK_DUP(a1, x1);
            PACK_DUP(a2, x2); PACK_DUP(a3, x3);
            const ulonglong2* wr = (const ulonglong2*)&W2c[kk * 32 + half * 16];
#pragma unroll
            for (int q = 0; q < 4; ++q) {
                ulonglong2 b = wr[q];          // cols half*16 + 4q..4q+3 (broadcast)
                FMA2(acc[0][2 * q],     a0, b.x); FMA2(acc[0][2 * q + 1], a0, b.y);
                FMA2(acc[1][2 * q],     a1, b.x); FMA2(acc[1][2 * q + 1], a1, b.y);
                FMA2(acc[2][2 * q],     a2, b.x); FMA2(acc[2][2 * q + 1], a2, b.y);
                FMA2(acc[3][2 * q],     a3, b.x); FMA2(acc[3][2 * q + 1], a3, b.y);
            }
        }
        __syncthreads();
    }

    // ---- X2 = relu(acc), stride 33 ----
    float* X2  = sm;           // 256*33 = 8448
    float* wsh = sm + 8448;    // 256
#pragma unroll
    for (int r = 0; r < 4; ++r) {
        int row = g + 64 * r;
#pragma unroll
        for (int q = 0; q < 8; ++q) {
            float lo, hi;
            UNPK(lo, hi, acc[r][q]);
            int cc = half * 16 + 2 * q;
            X2[row * 33 + cc]     = fmaxf(lo, 0.f);
            X2[row * 33 + cc + 1] = fmaxf(hi, 0.f);
        }
    }
    __syncthreads();

    // ---- logits + softmax (two peds per thread: p and p+8) ----
    {
        int p = tid >> 4, t = tid & 15;
        float lg0 = bats[t], lg1 = bats[t];
        const float* wa = Wag + t;
#pragma unroll 4
        for (int k = 0; k < 512; ++k) {
            int m = k >> 5, cc = k & 31;
            float wv = __ldg(&wa[k * 16]);
            lg0 = fmaf(X2[(p * 16 + m) * 33 + cc], wv, lg0);
            lg1 = fmaf(X2[((p + 8) * 16 + m) * 33 + cc], wv, lg1);
        }
        float mx0 = lg0, mx1 = lg1;
#pragma unroll
        for (int o = 8; o; o >>= 1) {
            mx0 = fmaxf(mx0, __shfl_xor_sync(0xffffffffu, mx0, o, 16));
            mx1 = fmaxf(mx1, __shfl_xor_sync(0xffffffffu, mx1, o, 16));
        }
        float e0 = expf(lg0 - mx0), e1 = expf(lg1 - mx1);
        float s0 = e0, s1 = e1;
#pragma unroll
        for (int o = 8; o; o >>= 1) {
            s0 += __shfl_xor_sync(0xffffffffu, s0, o, 16);
            s1 += __shfl_xor_sync(0xffffffffu, s1, o, 16);
        }
        wsh[p * 16 + t]       = e0 / s0;
        wsh[(p + 8) * 16 + t] = e1 / s1;
    }
    __syncthreads();

    // ---- weighted pool: 16 peds x 32 cols ----
    for (int o = tid; o < 512; o += 128) {
        int pp = o >> 5, cc = o & 31;
        int gp = pg * 16 + pp;
        if (gp < N_) {
            float a = 0.f;
#pragma unroll
            for (int m = 0; m < MAXC; ++m)
                a = fmaf(X2[(pp * 16 + m) * 33 + cc], wsh[pp * 16 + m], a);
            out[(size_t)(base + gp) * BN_ + cc] = a;
        }
    }
}

extern "C" void kernel_launch(void* const* d_in, const int* in_sizes, int n_in,
                              void* d_out, int out_size) {
    const float* h_st  = (const float*)d_in[0];
    const float* lp    = (const float*)d_in[1];
    const float* W_pos = (const float*)d_in[2];
    const float* b_pos = (const float*)d_in[3];
    const float* W1    = (const float*)d_in[4];
    const float* b1    = (const float*)d_in[5];
    const float* W2    = (const float*)d_in[6];
    const float* b2    = (const float*)d_in[7];
    const float* Wa    = (const float*)d_in[8];
    const float* ba    = (const float*)d_in[9];
    float* out = (float*)d_out;

    cudaFuncSetAttribute(fused_kernel, cudaFuncAttributeMaxDynamicSharedMemorySize,
                         SM_FLOATS * (int)sizeof(float));

    prep_kernel<<<1, HID_>>>(W_pos, b_pos, W1, b1);
    rank_kernel<<<dim3(N_ / 8, S_), 256>>>(lp);
    y_kernel<<<dim3((NPED + 63) / 64, HID_ / 64), 256>>>(h_st, W1);
    fused_kernel<<<dim3(13, S_), 128, SM_FLOATS * (int)sizeof(float)>>>(
        lp, W2, b2, Wa, ba, out);
}

// round 11
// speedup vs baseline: 1.8264x; 1.8264x over previous
#include <cuda_runtime.h>
#include <cstdint>
#include <cstddef>

#define S_   250
#define N_   200
#define MAXC 16
#define H_   64
#define HID_ 512
#define BN_  32
#define NPED (S_*N_)

// ---- scratch (static __device__ arrays: allocation-free) ----
__device__ __align__(16) static float g_Y[(size_t)NPED * HID_];   // h @ W1[:64] + b1p
__device__               static int   g_sel[NPED * MAXC];         // ranks
__device__ __align__(16) static float g_wpe[2 * HID_];            // W_pos @ W1[64:]
__device__ __align__(16) static float g_b1p[HID_];                // b1 + b_pos @ W1[64:]

// ---- packed f32x2 helpers ----
#define FMA2(d, a, b) asm("fma.rn.f32x2 %0, %1, %2, %0;" : "+l"(d) : "l"(a), "l"(b))
#define PACK_DUP(d, x) asm("mov.b64 %0, {%1, %1};" : "=l"(d) : "f"(x))
#define UNPK(lo, hi, v) asm("mov.b64 {%0, %1}, %2;" : "=f"(lo), "=f"(hi) : "l"(v))

__global__ void prep_kernel(const float* __restrict__ W_pos, const float* __restrict__ b_pos,
                            const float* __restrict__ W1,    const float* __restrict__ b1) {
    int t = threadIdx.x; // 512 threads
    float s0 = 0.f, s1 = 0.f, sb = 0.f;
    for (int e = 0; e < 64; ++e) {
        float w = W1[(size_t)(64 + e) * HID_ + t];
        s0 += W_pos[e] * w;
        s1 += W_pos[64 + e] * w;
        sb += b_pos[e] * w;
    }
    g_wpe[t] = s0;
    g_wpe[HID_ + t] = s1;
    g_b1p[t] = b1[t] + sb;
}

__device__ __forceinline__ float distf(const float* px, const float* py,
                                       int j, float xi, float yi) {
    float dx = px[j] - xi;
    float dy = py[j] - yi;
    return __fsqrt_rn(__fadd_rn(__fmul_rn(dx, dx), __fmul_rn(dy, dy)));
}

__global__ void rank_kernel(const float* __restrict__ lp) {
    int s = blockIdx.y;
    __shared__ float px[N_], py[N_];
    int tid = threadIdx.x;
    for (int j = tid; j < N_; j += 256) {
        px[j] = lp[(size_t)(s * N_ + j) * 2];
        py[j] = lp[(size_t)(s * N_ + j) * 2 + 1];
    }
    __syncthreads();
    int w = tid >> 5, lane = tid & 31;
    int i = blockIdx.x * 8 + w;
    float xi = px[i], yi = py[i];

    float dl = distf(px, py, lane, xi, yi);
    float dm[MAXC];
#pragma unroll
    for (int m = 0; m < MAXC; ++m) dm[m] = __shfl_sync(0xffffffffu, dl, m);

    int cnt[MAXC];
#pragma unroll
    for (int m = 0; m < MAXC; ++m) cnt[m] = 0;
    for (int j = lane; j < N_; j += 32) {
        float d = distf(px, py, j, xi, yi);
#pragma unroll
        for (int m = 0; m < MAXC; ++m)
            cnt[m] += (int)((d < dm[m]) || (d == dm[m] && j < m));
    }
    int myr = 0;
#pragma unroll
    for (int m = 0; m < MAXC; ++m) {
        int tot = __reduce_add_sync(0xffffffffu, cnt[m]);
        if (lane == m) myr = tot;
    }
    if (lane < MAXC) g_sel[(s * N_ + i) * MAXC + lane] = myr;
}

__global__ void y_kernel(const float* __restrict__ h, const float* __restrict__ W1) {
    __shared__ __align__(16) float Ash[64 * 65];
    __shared__ __align__(16) float Bsh[64 * 64];
    int tid = threadIdx.x;
    int row0 = blockIdx.x * 64;
    int c0   = blockIdx.y * 64;
#pragma unroll
    for (int q = 0; q < 4; ++q) {
        int idx4 = tid + 256 * q;
        int row = idx4 >> 4, k4 = (idx4 & 15) << 2;
        float4 v = make_float4(0.f, 0.f, 0.f, 0.f);
        if (row0 + row < NPED) v = *(const float4*)&h[(size_t)(row0 + row) * H_ + k4];
        Ash[row * 65 + k4 + 0] = v.x; Ash[row * 65 + k4 + 1] = v.y;
        Ash[row * 65 + k4 + 2] = v.z; Ash[row * 65 + k4 + 3] = v.w;
    }
#pragma unroll
    for (int q = 0; q < 4; ++q) {
        int idx4 = tid + 256 * q;
        int k = idx4 >> 4, c4 = (idx4 & 15) << 2;
        *(float4*)&Bsh[k * 64 + c4] = *(const float4*)&W1[(size_t)k * HID_ + c0 + c4];
    }
    __syncthreads();
    int rg = tid >> 4, cg = tid & 15;
    float acc[4][4] = {};
#pragma unroll 16
    for (int k = 0; k < 64; ++k) {
        float a[4];
#pragma unroll
        for (int r = 0; r < 4; ++r) a[r] = Ash[(rg * 4 + r) * 65 + k];
        float4 b = *(const float4*)&Bsh[k * 64 + cg * 4];
#pragma unroll
        for (int r = 0; r < 4; ++r) {
            acc[r][0] += a[r] * b.x; acc[r][1] += a[r] * b.y;
            acc[r][2] += a[r] * b.z; acc[r][3] += a[r] * b.w;
        }
    }
    float4 bb = *(const float4*)&g_b1p[c0 + cg * 4];
#pragma unroll
    for (int r = 0; r < 4; ++r) {
        int row = row0 + rg * 4 + r;
        if (row < NPED)
            *(float4*)&g_Y[(size_t)row * HID_ + c0 + cg * 4] =
                make_float4(acc[r][0] + bb.x, acc[r][1] + bb.y,
                            acc[r][2] + bb.z, acc[r][3] + bb.w);
    }
}

// =====================================================================
// fused: chunked pipeline; coalesced gather -> X1T smem -> f32x2 GEMM
// thread tile: 4 rows x 16 cols.  half = tid>>6 (warp-uniform -> W2
// broadcast); g = tid&63 owns rows {g, g+64, g+128, g+192} (conflict-free).
// __launch_bounds__(128,4): cap regs at 128 so 4 blocks/SM fit (R10 lost
// the 4th block at 130 regs and regressed 1.76x from latency exposure).
// =====================================================================
#define KC     32
#define X1TS   257
#define O_X1T  0
#define O_W2C  8704
#define O_WP0  9728
#define O_WP1  10240
#define O_PX   10752
#define O_PY   10952
#define O_FX   11152
#define O_FY   11408
#define O_YR   11664
#define O_B2   11920
#define O_BAT  11952
#define SM_FLOATS 11968

__global__ __launch_bounds__(128, 4) void fused_kernel(
    const float* __restrict__ lp, const float* __restrict__ W2g,
    const float* __restrict__ b2g, const float* __restrict__ Wag,
    const float* __restrict__ bag, float* __restrict__ out) {
    extern __shared__ __align__(16) float sm[];
    float* X1T  = sm + O_X1T;
    float* W2c  = sm + O_W2C;
    float* wp0s = sm + O_WP0;
    float* wp1s = sm + O_WP1;
    float* px   = sm + O_PX;
    float* py   = sm + O_PY;
    float* fxs  = sm + O_FX;
    float* fys  = sm + O_FY;
    int*   yr   = (int*)(sm + O_YR);
    float* b2s  = sm + O_B2;
    float* bats = sm + O_BAT;

    const int tid  = threadIdx.x;
    const int w    = tid >> 5, lane = tid & 31;
    const int s    = blockIdx.y;
    const int pg   = blockIdx.x;
    const int base = s * N_;

    for (int k = tid; k < HID_; k += 128) {
        wp0s[k] = g_wpe[k];
        wp1s[k] = g_wpe[HID_ + k];
    }
    for (int j = tid; j < N_; j += 128) {
        float2 p = *(const float2*)&lp[(size_t)(base + j) * 2];
        px[j] = p.x; py[j] = p.y;
    }
    if (tid < BN_)  b2s[tid]  = b2g[tid];
    if (tid < MAXC) bats[tid] = bag[tid];
    __syncthreads();

    for (int o = tid; o < 256; o += 128) {
        int ped = o >> 4, m = o & 15;
        int ig = min(pg * 16 + ped, N_ - 1);
        int rk = g_sel[(base + ig) * MAXC + m];
        yr[o]  = base + rk;
        fxs[o] = px[rk] - px[ig];
        fys[o] = py[rk] - py[ig];
    }
    __syncthreads();

    // ---- thread tile: rows {g,g+64,g+128,g+192} x cols [half*16, half*16+16)
    const int half = tid >> 6;
    const int g    = tid & 63;

    unsigned long long acc[4][8];
#pragma unroll
    for (int q = 0; q < 8; ++q) {
        unsigned long long b = *(const unsigned long long*)&b2s[half * 16 + 2 * q];
        acc[0][q] = b; acc[1][q] = b; acc[2][q] = b; acc[3][q] = b;
    }

    const int r_in = w * 64 + (lane >> 3);   // build-phase row base
    const int k4   = (lane & 7) << 2;        // build-phase k offset

    for (int c = 0; c < 16; ++c) {
        const int k0 = c * KC;
        // ---- build X1T chunk (coalesced gather) ----
        float4 wv0 = *(const float4*)&wp0s[k0 + k4];
        float4 wv1 = *(const float4*)&wp1s[k0 + k4];
#pragma unroll
        for (int rr = 0; rr < 16; ++rr) {
            int r = r_in + rr * 4;
            float4 y = *(const float4*)&g_Y[(size_t)yr[r] * HID_ + k0 + k4];
            float fx = fxs[r], fy = fys[r];
            X1T[(k4 + 0) * X1TS + r] = fmaxf(fmaf(fx, wv0.x, fmaf(fy, wv1.x, y.x)), 0.f);
            X1T[(k4 + 1) * X1TS + r] = fmaxf(fmaf(fx, wv0.y, fmaf(fy, wv1.y, y.y)), 0.f);
            X1T[(k4 + 2) * X1TS + r] = fmaxf(fmaf(fx, wv0.z, fmaf(fy, wv1.z, y.z)), 0.f);
            X1T[(k4 + 3) * X1TS + r] = fmaxf(fmaf(fx, wv0.w, fmaf(fy, wv1.w, y.w)), 0.f);
        }
        // ---- W2 chunk: 1024 floats, coalesced ----
        *(float4*)&W2c[tid * 4]         = *(const float4*)&W2g[(size_t)k0 * 32 + tid * 4];
        *(float4*)&W2c[(tid + 128) * 4] = *(const float4*)&W2g[(size_t)k0 * 32 + (tid + 128) * 4];
        __syncthreads();

        // ---- consume: 32 k-steps, 4 rows x 16 cols per thread ----
#pragma unroll 4
        for (int kk = 0; kk < KC; ++kk) {
            const float* xrow = &X1T[kk * X1TS];
            float x0 = xrow[g];
            float x1 = xrow[g + 64];
            float x2 = xrow[g + 128];
            float x3 = xrow[g + 192];
            unsigned long long a0, a1, a2, a3;
            PACK_DUP(a0, x0); PACK_DUP(a1, x1);
            PACK_DUP(a2, x2); PACK_DUP(a3, x3);
            const ulonglong2* wr = (const ulonglong2*)&W2c[kk * 32 + half * 16];
#pragma unroll
            for (int q = 0; q < 4; ++q) {
                ulonglong2 b = wr[q];          // cols half*16 + 4q..4q+3 (broadcast)
                FMA2(acc[0][2 * q],     a0, b.x); FMA2(acc[0][2 * q + 1], a0, b.y);
                FMA2(acc[1][2 * q],     a1, b.x); FMA2(acc[1][2 * q + 1], a1, b.y);
                FMA2(acc[2][2 * q],     a2, b.x); FMA2(acc[2][2 * q + 1], a2, b.y);
                FMA2(acc[3][2 * q],     a3, b.x); FMA2(acc[3][2 * q + 1], a3, b.y);
            }
        }
        __syncthreads();
    }

    // ---- X2 = relu(acc), stride 33 ----
    float* X2  = sm;           // 256*33 = 8448
    float* wsh = sm + 8448;    // 256
#pragma unroll
    for (int r = 0; r < 4; ++r) {
        int row = g + 64 * r;
#pragma unroll
        for (int q = 0; q < 8; ++q) {
            float lo, hi;
            UNPK(lo, hi, acc[r][q]);
            int cc = half * 16 + 2 * q;
            X2[row * 33 + cc]     = fmaxf(lo, 0.f);
            X2[row * 33 + cc + 1] = fmaxf(hi, 0.f);
        }
    }
    __syncthreads();

    // ---- logits + softmax (two peds per thread: p and p+8) ----
    {
        int p = tid >> 4, t = tid & 15;
        float lg0 = bats[t], lg1 = bats[t];
        const float* wa = Wag + t;
#pragma unroll 4
        for (int k = 0; k < 512; ++k) {
            int m = k >> 5, cc = k & 31;
            float wv = __ldg(&wa[k * 16]);
            lg0 = fmaf(X2[(p * 16 + m) * 33 + cc], wv, lg0);
            lg1 = fmaf(X2[((p + 8) * 16 + m) * 33 + cc], wv, lg1);
        }
        float mx0 = lg0, mx1 = lg1;
#pragma unroll
        for (int o = 8; o; o >>= 1) {
            mx0 = fmaxf(mx0, __shfl_xor_sync(0xffffffffu, mx0, o, 16));
            mx1 = fmaxf(mx1, __shfl_xor_sync(0xffffffffu, mx1, o, 16));
        }
        float e0 = expf(lg0 - mx0), e1 = expf(lg1 - mx1);
        float s0 = e0, s1 = e1;
#pragma unroll
        for (int o = 8; o; o >>= 1) {
            s0 += __shfl_xor_sync(0xffffffffu, s0, o, 16);
            s1 += __shfl_xor_sync(0xffffffffu, s1, o, 16);
        }
        wsh[p * 16 + t]       = e0 / s0;
        wsh[(p + 8) * 16 + t] = e1 / s1;
    }
    __syncthreads();

    // ---- weighted pool: 16 peds x 32 cols ----
    for (int o = tid; o < 512; o += 128) {
        int pp = o >> 5, cc = o & 31;
        int gp = pg * 16 + pp;
        if (gp < N_) {
            float a = 0.f;
#pragma unroll
            for (int m = 0; m < MAXC; ++m)
                a = fmaf(X2[(pp * 16 + m) * 33 + cc], wsh[pp * 16 + m], a);
            out[(size_t)(base + gp) * BN_ + cc] = a;
        }
    }
}

extern "C" void kernel_launch(void* const* d_in, const int* in_sizes, int n_in,
                              void* d_out, int out_size) {
    const float* h_st  = (const float*)d_in[0];
    const float* lp    = (const float*)d_in[1];
    const float* W_pos = (const float*)d_in[2];
    const float* b_pos = (const float*)d_in[3];
    const float* W1    = (const float*)d_in[4];
    const float* b1    = (const float*)d_in[5];
    const float* W2    = (const float*)d_in[6];
    const float* b2    = (const float*)d_in[7];
    const float* Wa    = (const float*)d_in[8];
    const float* ba    = (const float*)d_in[9];
    float* out = (float*)d_out;

    cudaFuncSetAttribute(fused_kernel, cudaFuncAttributeMaxDynamicSharedMemorySize,
                         SM_FLOATS * (int)sizeof(float));

    prep_kernel<<<1, HID_>>>(W_pos, b_pos, W1, b1);
    rank_kernel<<<dim3(N_ / 8, S_), 256>>>(lp);
    y_kernel<<<dim3((NPED + 63) / 64, HID_ / 64), 256>>>(h_st, W1);
    fused_kernel<<<dim3(13, S_), 128, SM_FLOATS * (int)sizeof(float)>>>(
        lp, W2, b2, Wa, ba, out);
}

// round 12
// speedup vs baseline: 2.0545x; 1.1249x over previous
#include <cuda_runtime.h>
#include <cstdint>
#include <cstddef>

#define S_   250
#define N_   200
#define MAXC 16
#define H_   64
#define HID_ 512
#define BN_  32
#define NPED (S_*N_)

// ---- scratch (static __device__ arrays: allocation-free) ----
__device__ __align__(16) static float g_Y[(size_t)NPED * HID_];   // h @ W1[:64] + b1p
__device__               static int   g_sel[NPED * MAXC];         // ranks
__device__ __align__(16) static float g_wpe[2 * HID_];            // W_pos @ W1[64:]
__device__ __align__(16) static float g_b1p[HID_];                // b1 + b_pos @ W1[64:]

// ---- packed f32x2 helpers ----
#define FMA2(d, a, b) asm("fma.rn.f32x2 %0, %1, %2, %0;" : "+l"(d) : "l"(a), "l"(b))
#define PACK_DUP(d, x) asm("mov.b64 %0, {%1, %1};" : "=l"(d) : "f"(x))
#define UNPK(lo, hi, v) asm("mov.b64 {%0, %1}, %2;" : "=f"(lo), "=f"(hi) : "l"(v))

__global__ void prep_kernel(const float* __restrict__ W_pos, const float* __restrict__ b_pos,
                            const float* __restrict__ W1,    const float* __restrict__ b1) {
    int t = threadIdx.x; // 512 threads
    float s0 = 0.f, s1 = 0.f, sb = 0.f;
    for (int e = 0; e < 64; ++e) {
        float w = W1[(size_t)(64 + e) * HID_ + t];
        s0 += W_pos[e] * w;
        s1 += W_pos[64 + e] * w;
        sb += b_pos[e] * w;
    }
    g_wpe[t] = s0;
    g_wpe[HID_ + t] = s1;
    g_b1p[t] = b1[t] + sb;
}

__device__ __forceinline__ float distf(const float* px, const float* py,
                                       int j, float xi, float yi) {
    float dx = px[j] - xi;
    float dy = py[j] - yi;
    return __fsqrt_rn(__fadd_rn(__fmul_rn(dx, dx), __fmul_rn(dy, dy)));
}

__global__ void rank_kernel(const float* __restrict__ lp) {
    int s = blockIdx.y;
    __shared__ float px[N_], py[N_];
    int tid = threadIdx.x;
    for (int j = tid; j < N_; j += 256) {
        px[j] = lp[(size_t)(s * N_ + j) * 2];
        py[j] = lp[(size_t)(s * N_ + j) * 2 + 1];
    }
    __syncthreads();
    int w = tid >> 5, lane = tid & 31;
    int i = blockIdx.x * 8 + w;
    float xi = px[i], yi = py[i];

    float dl = distf(px, py, lane, xi, yi);
    float dm[MAXC];
#pragma unroll
    for (int m = 0; m < MAXC; ++m) dm[m] = __shfl_sync(0xffffffffu, dl, m);

    int cnt[MAXC];
#pragma unroll
    for (int m = 0; m < MAXC; ++m) cnt[m] = 0;
    for (int j = lane; j < N_; j += 32) {
        float d = distf(px, py, j, xi, yi);
#pragma unroll
        for (int m = 0; m < MAXC; ++m)
            cnt[m] += (int)((d < dm[m]) || (d == dm[m] && j < m));
    }
    int myr = 0;
#pragma unroll
    for (int m = 0; m < MAXC; ++m) {
        int tot = __reduce_add_sync(0xffffffffu, cnt[m]);
        if (lane == m) myr = tot;
    }
    if (lane < MAXC) g_sel[(s * N_ + i) * MAXC + lane] = myr;
}

__global__ void y_kernel(const float* __restrict__ h, const float* __restrict__ W1) {
    __shared__ __align__(16) float Ash[64 * 65];
    __shared__ __align__(16) float Bsh[64 * 64];
    int tid = threadIdx.x;
    int row0 = blockIdx.x * 64;
    int c0   = blockIdx.y * 64;
#pragma unroll
    for (int q = 0; q < 4; ++q) {
        int idx4 = tid + 256 * q;
        int row = idx4 >> 4, k4 = (idx4 & 15) << 2;
        float4 v = make_float4(0.f, 0.f, 0.f, 0.f);
        if (row0 + row < NPED) v = *(const float4*)&h[(size_t)(row0 + row) * H_ + k4];
        Ash[row * 65 + k4 + 0] = v.x; Ash[row * 65 + k4 + 1] = v.y;
        Ash[row * 65 + k4 + 2] = v.z; Ash[row * 65 + k4 + 3] = v.w;
    }
#pragma unroll
    for (int q = 0; q < 4; ++q) {
        int idx4 = tid + 256 * q;
        int k = idx4 >> 4, c4 = (idx4 & 15) << 2;
        *(float4*)&Bsh[k * 64 + c4] = *(const float4*)&W1[(size_t)k * HID_ + c0 + c4];
    }
    __syncthreads();
    int rg = tid >> 4, cg = tid & 15;
    float acc[4][4] = {};
#pragma unroll 16
    for (int k = 0; k < 64; ++k) {
        float a[4];
#pragma unroll
        for (int r = 0; r < 4; ++r) a[r] = Ash[(rg * 4 + r) * 65 + k];
        float4 b = *(const float4*)&Bsh[k * 64 + cg * 4];
#pragma unroll
        for (int r = 0; r < 4; ++r) {
            acc[r][0] += a[r] * b.x; acc[r][1] += a[r] * b.y;
            acc[r][2] += a[r] * b.z; acc[r][3] += a[r] * b.w;
        }
    }
    float4 bb = *(const float4*)&g_b1p[c0 + cg * 4];
#pragma unroll
    for (int r = 0; r < 4; ++r) {
        int row = row0 + rg * 4 + r;
        if (row < NPED)
            *(float4*)&g_Y[(size_t)row * HID_ + c0 + cg * 4] =
                make_float4(acc[r][0] + bb.x, acc[r][1] + bb.y,
                            acc[r][2] + bb.z, acc[r][3] + bb.w);
    }
}

// =====================================================================
// fused: software-pipelined double-buffered chunks (KC=16).
// Per iter: LDG(next) -> consume 8k(prev) -> STS A + LDG B -> consume 8k
// -> STS B -> ONE barrier.  Thread tile 4 rows x 16 cols (f32x2).
// X1TS=258 (== 2 mod 32): build STS banks 8a+d distinct; consume banks
// g+2kk distinct.  Same accumulation order as R11 -> identical rel_err.
// =====================================================================
#define KC     16
#define X1TS   258
#define X1BUF  (KC * X1TS)          // 4128
#define O_X1T  0                    // 2*4128 = 8256 (reused by X2 8448+wsh 256)
#define O_W2C  8256                 // 2*512 = 1024 (dead before X2's 8448 tail use)
#define O_WP0  9280
#define O_WP1  9792
#define O_PX   10304
#define O_PY   10504
#define O_FX   10704
#define O_FY   10960
#define O_YR   11216
#define O_B2   11472
#define O_BAT  11504
#define SM_FLOATS 11520

__global__ __launch_bounds__(128, 4) void fused_kernel(
    const float* __restrict__ lp, const float* __restrict__ W2g,
    const float* __restrict__ b2g, const float* __restrict__ Wag,
    const float* __restrict__ bag, float* __restrict__ out) {
    extern __shared__ __align__(16) float sm[];
    float* X1T  = sm + O_X1T;
    float* W2c  = sm + O_W2C;
    float* wp0s = sm + O_WP0;
    float* wp1s = sm + O_WP1;
    float* px   = sm + O_PX;
    float* py   = sm + O_PY;
    float* fxs  = sm + O_FX;
    float* fys  = sm + O_FY;
    int*   yr   = (int*)(sm + O_YR);
    float* b2s  = sm + O_B2;
    float* bats = sm + O_BAT;

    const int tid  = threadIdx.x;
    const int w    = tid >> 5, lane = tid & 31;
    const int s    = blockIdx.y;
    const int pg   = blockIdx.x;
    const int base = s * N_;

    for (int k = tid; k < HID_; k += 128) {
        wp0s[k] = g_wpe[k];
        wp1s[k] = g_wpe[HID_ + k];
    }
    for (int j = tid; j < N_; j += 128) {
        float2 p = *(const float2*)&lp[(size_t)(base + j) * 2];
        px[j] = p.x; py[j] = p.y;
    }
    if (tid < BN_)  b2s[tid]  = b2g[tid];
    if (tid < MAXC) bats[tid] = bag[tid];
    __syncthreads();

    for (int o = tid; o < 256; o += 128) {
        int ped = o >> 4, m = o & 15;
        int ig = min(pg * 16 + ped, N_ - 1);
        int rk = g_sel[(base + ig) * MAXC + m];
        yr[o]  = base + rk;
        fxs[o] = px[rk] - px[ig];
        fys[o] = py[rk] - py[ig];
    }
    __syncthreads();

    // consume mapping: rows {g, g+64, g+128, g+192}, cols [half*16, +16)
    const int half = tid >> 6;
    const int g    = tid & 63;
    // build mapping: k quartet (lane&3)*4 within chunk, rows w*64 + (lane>>2) + 8t
    const int k4b  = (lane & 3) << 2;
    const int brow = w * 64 + (lane >> 2);

    unsigned long long acc[4][8];
#pragma unroll
    for (int q = 0; q < 8; ++q) {
        unsigned long long b = *(const unsigned long long*)&b2s[half * 16 + 2 * q];
        acc[0][q] = b; acc[1][q] = b; acc[2][q] = b; acc[3][q] = b;
    }

    // one transformed store: row r of build-buffer `buf`
    auto sts1 = [&](int buf, int r, float4 y, const float4& wv0, const float4& wv1) {
        float fx = fxs[r], fy = fys[r];
        float* xb = &X1T[buf * X1BUF + r];
        xb[(k4b + 0) * X1TS] = fmaxf(fmaf(fx, wv0.x, fmaf(fy, wv1.x, y.x)), 0.f);
        xb[(k4b + 1) * X1TS] = fmaxf(fmaf(fx, wv0.y, fmaf(fy, wv1.y, y.y)), 0.f);
        xb[(k4b + 2) * X1TS] = fmaxf(fmaf(fx, wv0.z, fmaf(fy, wv1.z, y.z)), 0.f);
        xb[(k4b + 3) * X1TS] = fmaxf(fmaf(fx, wv0.w, fmaf(fy, wv1.w, y.w)), 0.f);
    };
    auto consume8 = [&](int buf, int kb) {
#pragma unroll
        for (int kk = 0; kk < 8; ++kk) {
            const float* xb = &X1T[buf * X1BUF + (kb + kk) * X1TS];
            float x0 = xb[g], x1 = xb[g + 64], x2 = xb[g + 128], x3 = xb[g + 192];
            unsigned long long a0, a1, a2, a3;
            PACK_DUP(a0, x0); PACK_DUP(a1, x1);
            PACK_DUP(a2, x2); PACK_DUP(a3, x3);
            const ulonglong2* wr =
                (const ulonglong2*)&W2c[buf * 512 + (kb + kk) * 32 + half * 16];
#pragma unroll
            for (int q = 0; q < 4; ++q) {
                ulonglong2 b = wr[q];
                FMA2(acc[0][2 * q], a0, b.x); FMA2(acc[0][2 * q + 1], a0, b.y);
                FMA2(acc[1][2 * q], a1, b.x); FMA2(acc[1][2 * q + 1], a1, b.y);
                FMA2(acc[2][2 * q], a2, b.x); FMA2(acc[2][2 * q + 1], a2, b.y);
                FMA2(acc[3][2 * q], a3, b.x); FMA2(acc[3][2 * q + 1], a3, b.y);
            }
        }
    };

    // ---- prologue: build chunk 0 into buf 0 ----
    {
        float4 wv0 = *(const float4*)&wp0s[k4b];
        float4 wv1 = *(const float4*)&wp1s[k4b];
#pragma unroll
        for (int t = 0; t < 8; ++t) {
            int r = brow + 8 * t;
            float4 y = *(const float4*)&g_Y[(size_t)yr[r] * HID_ + k4b];
            sts1(0, r, y, wv0, wv1);
        }
        *(float4*)&W2c[tid * 4] = *(const float4*)&W2g[tid * 4];
    }
    __syncthreads();

    // ---- pipelined mainloop ----
    for (int c = 1; c < 32; ++c) {
        const int cb = c & 1, pb = cb ^ 1;
        const int k0b = c * KC;
        float4 wv0 = *(const float4*)&wp0s[k0b + k4b];
        float4 wv1 = *(const float4*)&wp1s[k0b + k4b];
        float4 w2pf = *(const float4*)&W2g[(size_t)k0b * 32 + tid * 4];
        float4 pf0 = *(const float4*)&g_Y[(size_t)yr[brow     ] * HID_ + k0b + k4b];
        float4 pf1 = *(const float4*)&g_Y[(size_t)yr[brow +  8] * HID_ + k0b + k4b];
        float4 pf2 = *(const float4*)&g_Y[(size_t)yr[brow + 16] * HID_ + k0b + k4b];
        float4 pf3 = *(const float4*)&g_Y[(size_t)yr[brow + 24] * HID_ + k0b + k4b];

        consume8(pb, 0);

        sts1(cb, brow,      pf0, wv0, wv1);
        sts1(cb, brow +  8, pf1, wv0, wv1);
        sts1(cb, brow + 16, pf2, wv0, wv1);
        sts1(cb, brow + 24, pf3, wv0, wv1);
        pf0 = *(const float4*)&g_Y[(size_t)yr[brow + 32] * HID_ + k0b + k4b];
        pf1 = *(const float4*)&g_Y[(size_t)yr[brow + 40] * HID_ + k0b + k4b];
        pf2 = *(const float4*)&g_Y[(size_t)yr[brow + 48] * HID_ + k0b + k4b];
        pf3 = *(const float4*)&g_Y[(size_t)yr[brow + 56] * HID_ + k0b + k4b];
        *(float4*)&W2c[cb * 512 + tid * 4] = w2pf;

        consume8(pb, 8);

        sts1(cb, brow + 32, pf0, wv0, wv1);
        sts1(cb, brow + 40, pf1, wv0, wv1);
        sts1(cb, brow + 48, pf2, wv0, wv1);
        sts1(cb, brow + 56, pf3, wv0, wv1);
        __syncthreads();
    }
    // ---- final consume: chunk 31 in buf 1 ----
    consume8(1, 0);
    consume8(1, 8);
    __syncthreads();   // X2 below overwrites X1T region

    // ---- X2 = relu(acc), stride 33 ----
    float* X2  = sm;           // 256*33 = 8448
    float* wsh = sm + 8448;    // 256
#pragma unroll
    for (int r = 0; r < 4; ++r) {
        int row = g + 64 * r;
#pragma unroll
        for (int q = 0; q < 8; ++q) {
            float lo, hi;
            UNPK(lo, hi, acc[r][q]);
            int cc = half * 16 + 2 * q;
            X2[row * 33 + cc]     = fmaxf(lo, 0.f);
            X2[row * 33 + cc + 1] = fmaxf(hi, 0.f);
        }
    }
    __syncthreads();

    // ---- logits + softmax (two peds per thread: p and p+8) ----
    {
        int p = tid >> 4, t = tid & 15;
        float lg0 = bats[t], lg1 = bats[t];
        const float* wa = Wag + t;
#pragma unroll 4
        for (int k = 0; k < 512; ++k) {
            int m = k >> 5, cc = k & 31;
            float wv = __ldg(&wa[k * 16]);
            lg0 = fmaf(X2[(p * 16 + m) * 33 + cc], wv, lg0);
            lg1 = fmaf(X2[((p + 8) * 16 + m) * 33 + cc], wv, lg1);
        }
        float mx0 = lg0, mx1 = lg1;
#pragma unroll
        for (int o = 8; o; o >>= 1) {
            mx0 = fmaxf(mx0, __shfl_xor_sync(0xffffffffu, mx0, o, 16));
            mx1 = fmaxf(mx1, __shfl_xor_sync(0xffffffffu, mx1, o, 16));
        }
        float e0 = expf(lg0 - mx0), e1 = expf(lg1 - mx1);
        float s0 = e0, s1 = e1;
#pragma unroll
        for (int o = 8; o; o >>= 1) {
            s0 += __shfl_xor_sync(0xffffffffu, s0, o, 16);
            s1 += __shfl_xor_sync(0xffffffffu, s1, o, 16);
        }
        wsh[p * 16 + t]       = e0 / s0;
        wsh[(p + 8) * 16 + t] = e1 / s1;
    }
    __syncthreads();

    // ---- weighted pool: 16 peds x 32 cols ----
    for (int o = tid; o < 512; o += 128) {
        int pp = o >> 5, cc = o & 31;
        int gp = pg * 16 + pp;
        if (gp < N_) {
            float a = 0.f;
#pragma unroll
            for (int m = 0; m < MAXC; ++m)
                a = fmaf(X2[(pp * 16 + m) * 33 + cc], wsh[pp * 16 + m], a);
            out[(size_t)(base + gp) * BN_ + cc] = a;
        }
    }
}

extern "C" void kernel_launch(void* const* d_in, const int* in_sizes, int n_in,
                              void* d_out, int out_size) {
    const float* h_st  = (const float*)d_in[0];
    const float* lp    = (const float*)d_in[1];
    const float* W_pos = (const float*)d_in[2];
    const float* b_pos = (const float*)d_in[3];
    const float* W1    = (const float*)d_in[4];
    const float* b1    = (const float*)d_in[5];
    const float* W2    = (const float*)d_in[6];
    const float* b2    = (const float*)d_in[7];
    const float* Wa    = (const float*)d_in[8];
    const float* ba    = (const float*)d_in[9];
    float* out = (float*)d_out;

    cudaFuncSetAttribute(fused_kernel, cudaFuncAttributeMaxDynamicSharedMemorySize,
                         SM_FLOATS * (int)sizeof(float));

    prep_kernel<<<1, HID_>>>(W_pos, b_pos, W1, b1);
    rank_kernel<<<dim3(N_ / 8, S_), 256>>>(lp);
    y_kernel<<<dim3((NPED + 63) / 64, HID_ / 64), 256>>>(h_st, W1);
    fused_kernel<<<dim3(13, S_), 128, SM_FLOATS * (int)sizeof(float)>>>(
        lp, W2, b2, Wa, ba, out);
}